// round 16
// baseline (speedup 1.0000x reference)
#include <cuda_runtime.h>
#include <cuda_fp16.h>
#include <cstdint>

#define BB 32
#define TT 512
#define KK 48
#define TILESZ (KK * KK)     // contiguous fp32 tile
#define NTH 96               // 3 warps -> 1 per SMSP
#define NB 6
#define START_TAG 46
#define STOP_TAG 47

__device__ float g_partials[BB];
__device__ int   g_ctr = 0;

__device__ __forceinline__ float ex2f(float x) {
    float y; asm("ex2.approx.ftz.f32 %0, %1;" : "=f"(y) : "f"(x)); return y;
}
__device__ __forceinline__ float lg2f(float x) {
    float y; asm("lg2.approx.ftz.f32 %0, %1;" : "=f"(y) : "f"(x)); return y;
}
__device__ __forceinline__ void cp16(uint32_t smem, const void* g) {
    asm volatile("cp.async.cg.shared.global [%0], [%1], 16;" :: "r"(smem), "l"(g));
}
__device__ __forceinline__ void cp_commit() { asm volatile("cp.async.commit_group;"); }
__device__ __forceinline__ void cp_wait3()  { asm volatile("cp.async.wait_group 3;"); }
__device__ __forceinline__ void cp_wait4()  { asm volatile("cp.async.wait_group 4;"); }

__device__ __forceinline__ uint32_t ex2_cvt(float f0, float f1, uint32_t l2e2) {
    uint32_t p, r;
    asm("cvt.rn.f16x2.f32 %0, %1, %2;" : "=r"(p) : "f"(f1), "f"(f0));  // hi=f1, lo=f0
    asm("mul.f16x2 %0, %0, %1;" : "+r"(p) : "r"(l2e2));
    asm volatile("ex2.approx.f16x2 %0, %1;" : "=r"(r) : "r"(p));
    return r;
}
__device__ __forceinline__ uint32_t hfma2(uint32_t a, uint32_t b, uint32_t c) {
    uint32_t d; asm("fma.rn.f16x2 %0, %1, %2, %3;" : "=r"(d) : "r"(a), "r"(b), "r"(c)); return d;
}
__device__ __forceinline__ uint32_t hmul2(uint32_t a, uint32_t b) {
    uint32_t d; asm("mul.f16x2 %0, %1, %2;" : "=r"(d) : "r"(a), "r"(b)); return d;
}
__device__ __forceinline__ uint32_t hadd2(uint32_t a, uint32_t b) {
    uint32_t d; asm("add.f16x2 %0, %1, %2;" : "=r"(d) : "r"(a), "r"(b)); return d;
}
__device__ __forceinline__ uint32_t prmt(uint32_t a, uint32_t sel) {
    uint32_t d; asm("prmt.b32 %0, %1, %1, %2;" : "=r"(d) : "r"(a), "r"(sel)); return d;
}

// carry slot for tag i: lane-u's 12 carries contiguous -> 3x LDS.128
__device__ __forceinline__ int pslot(int i) { return (i & 3) * 12 + (i >> 2); }

extern __shared__ float smem_dyn[];

__global__ __launch_bounds__(NTH, 1)
void crf_fwd_kernel(const float* __restrict__ feat,
                    const int*   __restrict__ targets,
                    const int*   __restrict__ lengths,
                    float*       __restrict__ out)
{
    float*    tile = smem_dyn;                         // NB * TILESZ fp32
    uint32_t* ch   = (uint32_t*)(tile + NB * TILESZ);  // 2 x 48 packed (c,c) f16x2, permuted
    float*    gred = (float*)(ch + 2 * KK);            // 3 warp gold partials

    const int b   = blockIdx.x;
    const int tid = threadIdx.x;
    const int len = lengths[b];
    const float* fb = feat + (size_t)b * TT * (KK * KK);

    const int l = tid & 31;
    const int w = tid >> 5;
    const int p = 8 * w + (l & 7);   // column pair -> cols 2p, 2p+1
    const int u = l >> 3;            // i = u + 4*k

    const uint32_t L2E2 = 0x3DC53DC5u;   // half(log2e) duplicated
    const float LN2 = 0.6931471805599453f;

    uint32_t sb[NB];
    #pragma unroll
    for (int n = 0; n < NB; ++n)
        sb[n] = (uint32_t)__cvta_generic_to_shared(tile + n * TILESZ);

    // -------- gold: gathered once from global (off the recursion loop) --------
    float gold = 0.f;
    {
        const int* tg = targets + b * TT;
        #pragma unroll
        for (int q = 0; q < 6; ++q) {
            int t = tid + q * NTH;
            if (t < len) {
                int v = __ldg(tg + t);
                gold += __ldg(fb + (size_t)t * TILESZ + v);
            }
        }
    }

    // -------- prologue: tiles 0..4 as 5 groups --------
    #pragma unroll
    for (int tt = 0; tt < 5; ++tt) {
        if (tt < len) {
            const float* src = fb + (size_t)tt * TILESZ;
            #pragma unroll
            for (int q = 0; q < 6; ++q)
                cp16(sb[tt] + (tid + q * NTH) * 16, src + (tid + q * NTH) * 4);
        }
        cp_commit();
    }
    cp_wait4();
    __syncthreads();       // tile 0 visible

    // init packed carries s_0 = c_0 * 2^-4 at permuted slots, buffer 0
    if (tid < KK) {
        float c = ex2f(tile[KK * START_TAG + tid] * 1.4426950408889634f);
        __half h = __float2half_rn(c * 0.0625f);
        uint32_t hb = (uint32_t)__half_as_ushort(h);
        ch[pslot(tid)] = hb | (hb << 16);
    }
    int eacc = 0;

    cp_wait3();
    __syncthreads();       // tile 1 visible

    // E for tile 1 (24 elements = 12 packed f16x2; i = u + 4*k)
    uint32_t E2[12];
    {
        const float* fn = tile + 1 * TILESZ + u * KK + 2 * p;
        #pragma unroll
        for (int k = 0; k < 12; ++k) {
            float2 f = *(const float2*)(fn + KK * 4 * k);
            E2[k] = ex2_cvt(f.x, f.y, L2E2);
        }
    }
    if (5 < len) {
        const float* src = fb + (size_t)5 * TILESZ;
        #pragma unroll
        for (int q = 0; q < 6; ++q)
            cp16(sb[5] + (tid + q * NTH) * 16, src + (tid + q * NTH) * 4);
    }
    cp_commit();

    int cur = 1;   // t % NB
    int pfb = 0;   // (t+5) % NB
    for (int t = 1; t < len; ++t) {
        cp_wait3();
        __syncthreads();     // carries(t-1) + tile t+1 visible; buffer pfb drained

        const uint32_t* cr = ch + ((t - 1) & 1) * KK;

        // carries: 3 x LDS.128 (broadcast within u-group) + c0 word
        uint4 Ca = *(const uint4*)(cr + u * 12);
        uint4 Cb = *(const uint4*)(cr + u * 12 + 4);
        uint4 Cc = *(const uint4*)(cr + u * 12 + 8);
        uint32_t ch0 = cr[0];

        // dot over 12 i-values, both columns at once
        uint32_t aa = hmul2(E2[0], Ca.x);
        uint32_t bb = hmul2(E2[1], Ca.y);
        aa = hfma2(E2[2],  Ca.z, aa);
        bb = hfma2(E2[3],  Ca.w, bb);
        aa = hfma2(E2[4],  Cb.x, aa);
        bb = hfma2(E2[5],  Cb.y, bb);
        aa = hfma2(E2[6],  Cb.z, aa);
        bb = hfma2(E2[7],  Cb.w, bb);
        aa = hfma2(E2[8],  Cc.x, aa);
        bb = hfma2(E2[9],  Cc.y, bb);
        aa = hfma2(E2[10], Cc.z, aa);
        bb = hfma2(E2[11], Cc.w, bb);
        uint32_t acc = hadd2(aa, bb);

        // first reduction stage; issue second shuffle, consume it after E-block
        acc = hadd2(acc, __shfl_xor_sync(0xffffffffu, acc, 8));
        uint32_t s2 = __shfl_xor_sync(0xffffffffu, acc, 16);

        // prefetch tile t+5 (off the chain)
        {
            int tn = t + 5;
            if (tn < len) {
                const float* src = fb + (size_t)tn * TILESZ;
                uint32_t dst = sb[pfb];
                #pragma unroll
                for (int q = 0; q < 6; ++q)
                    cp16(dst + (tid + q * NTH) * 16, src + (tid + q * NTH) * 4);
            }
            cp_commit();
        }

        // E for tile t+1 (pinned EX2s; drains over shfl2 latency)
        {
            const float* fn = tile + ((cur + 1 == NB) ? 0 : cur + 1) * TILESZ + u * KK + 2 * p;
            #pragma unroll
            for (int k = 0; k < 12; ++k) {
                float2 f = *(const float2*)(fn + KK * 4 * k);
                E2[k] = ex2_cvt(f.x, f.y, L2E2);
            }
        }

        // finish reduction, renorm (lagged, T = -8), store
        acc = hadd2(acc, s2);
        const int be = (int)((ch0 >> 10) & 31);
        eacc += be;
        if (u == 0) {
            const uint32_t rb = (uint32_t)(22 - be) << 10;
            acc = hmul2(acc, rb | (rb << 16));
            uint32_t d0 = prmt(acc, 0x1010);   // (lo,lo) -> col 2p
            uint32_t d1 = prmt(acc, 0x3232);   // (hi,hi) -> col 2p+1
            uint32_t* cw = ch + (t & 1) * KK;
            cw[pslot(2 * p)]     = d0;
            cw[pslot(2 * p + 1)] = d1;
        }

        if (++cur == NB) cur = 0;
        if (++pfb == NB) pfb = 0;
    }

    // -------- gold reduction (deterministic fixed order) --------
    #pragma unroll
    for (int o = 16; o; o >>= 1) gold += __shfl_down_sync(0xffffffffu, gold, o);
    if (l == 0) gred[w] = gold;
    __syncthreads();

    if (tid == 0) {
        float g = (gred[0] + gred[1]) + gred[2];
        uint32_t sw = ch[((len - 1) & 1) * KK + pslot(STOP_TAG)];
        float s = __half2float(__ushort_as_half((unsigned short)(sw & 0xFFFF)));
        float fin = (lg2f(s) + 4.0f + (float)eacc - 7.0f * (float)(len - 1)) * LN2;
        g_partials[b] = fin - g;
    }

    // fused deterministic batch reduction (last block)
    if (tid < 32) {
        int old = 0;
        if (tid == 0) {
            __threadfence();
            old = atomicAdd(&g_ctr, 1);
        }
        old = __shfl_sync(0xffffffffu, old, 0);
        if (old == BB - 1) {
            __threadfence();
            float v = g_partials[tid];
            #pragma unroll
            for (int o = 16; o; o >>= 1) v += __shfl_down_sync(0xffffffffu, v, o);
            if (tid == 0) { out[0] = v / (float)BB; g_ctr = 0; }
        }
    }
}

extern "C" void kernel_launch(void* const* d_in, const int* in_sizes, int n_in,
                              void* d_out, int out_size)
{
    const float* feat    = (const float*)d_in[0];
    const int*   targets = (const int*)d_in[1];
    const int*   lengths = (const int*)d_in[2];
    float*       out     = (float*)d_out;

    const int smem_bytes = NB * TILESZ * 4 + 2 * KK * 4 + 16;  // ~55.7 KB
    cudaFuncSetAttribute(crf_fwd_kernel, cudaFuncAttributeMaxDynamicSharedMemorySize, smem_bytes);
    crf_fwd_kernel<<<BB, NTH, smem_bytes>>>(feat, targets, lengths, out);
}

// round 17
// speedup vs baseline: 1.0185x; 1.0185x over previous
#include <cuda_runtime.h>
#include <cuda_fp16.h>
#include <cstdint>

#define BB 32
#define TT 512
#define KK 48
#define TILESZ (KK * KK)     // contiguous fp32 tile
#define NTH 96               // 3 warps -> 1 per SMSP
#define NB 6
#define START_TAG 46
#define STOP_TAG 47

__device__ float g_partials[BB];
__device__ int   g_ctr = 0;

__device__ __forceinline__ float ex2f(float x) {
    float y; asm("ex2.approx.ftz.f32 %0, %1;" : "=f"(y) : "f"(x)); return y;
}
__device__ __forceinline__ float lg2f(float x) {
    float y; asm("lg2.approx.ftz.f32 %0, %1;" : "=f"(y) : "f"(x)); return y;
}
__device__ __forceinline__ void cp16(uint32_t smem, const void* g) {
    asm volatile("cp.async.cg.shared.global [%0], [%1], 16;" :: "r"(smem), "l"(g));
}
__device__ __forceinline__ void cp_commit() { asm volatile("cp.async.commit_group;"); }
__device__ __forceinline__ void cp_wait3()  { asm volatile("cp.async.wait_group 3;"); }
__device__ __forceinline__ void cp_wait4()  { asm volatile("cp.async.wait_group 4;"); }

__device__ __forceinline__ uint32_t ex2_cvt(float f0, float f1, uint32_t l2e2) {
    uint32_t p, r;
    asm("cvt.rn.f16x2.f32 %0, %1, %2;" : "=r"(p) : "f"(f1), "f"(f0));  // hi=f1, lo=f0
    asm("mul.f16x2 %0, %0, %1;" : "+r"(p) : "r"(l2e2));
    asm volatile("ex2.approx.f16x2 %0, %1;" : "=r"(r) : "r"(p));
    return r;
}
__device__ __forceinline__ uint32_t hfma2(uint32_t a, uint32_t b, uint32_t c) {
    uint32_t d; asm("fma.rn.f16x2 %0, %1, %2, %3;" : "=r"(d) : "r"(a), "r"(b), "r"(c)); return d;
}
__device__ __forceinline__ uint32_t hmul2(uint32_t a, uint32_t b) {
    uint32_t d; asm("mul.f16x2 %0, %1, %2;" : "=r"(d) : "r"(a), "r"(b)); return d;
}
__device__ __forceinline__ uint32_t hadd2(uint32_t a, uint32_t b) {
    uint32_t d; asm("add.f16x2 %0, %1, %2;" : "=r"(d) : "r"(a), "r"(b)); return d;
}
__device__ __forceinline__ uint32_t prmt(uint32_t a, uint32_t sel) {
    uint32_t d; asm("prmt.b32 %0, %1, %1, %2;" : "=r"(d) : "r"(a), "r"(sel)); return d;
}

extern __shared__ float smem_dyn[];

__global__ __launch_bounds__(NTH, 1)
void crf_fwd_kernel(const float* __restrict__ feat,
                    const int*   __restrict__ targets,
                    const int*   __restrict__ lengths,
                    float*       __restrict__ out)
{
    float*    tile = smem_dyn;                         // NB * TILESZ fp32
    uint32_t* ch   = (uint32_t*)(tile + NB * TILESZ);  // 2 x 48 packed (c,c) f16x2
    float*    gred = (float*)(ch + 2 * KK);            // 3 warp gold partials

    const int b   = blockIdx.x;
    const int tid = threadIdx.x;
    const int len = lengths[b];
    const float* fb = feat + (size_t)b * TT * (KK * KK);

    const int l = tid & 31;
    const int w = tid >> 5;
    const int p = 8 * w + (l & 7);   // column pair -> cols 2p, 2p+1
    const int u = l >> 3;            // i = u + 4*k

    const uint32_t L2E2 = 0x3DC53DC5u;   // half(log2e) duplicated
    const float LN2 = 0.6931471805599453f;

    uint32_t sb[NB];
    #pragma unroll
    for (int n = 0; n < NB; ++n)
        sb[n] = (uint32_t)__cvta_generic_to_shared(tile + n * TILESZ);

    // -------- prologue: tiles 0..4 as 5 groups --------
    #pragma unroll
    for (int tt = 0; tt < 5; ++tt) {
        if (tt < len) {
            const float* src = fb + (size_t)tt * TILESZ;
            #pragma unroll
            for (int q = 0; q < 6; ++q)
                cp16(sb[tt] + (tid + q * NTH) * 16, src + (tid + q * NTH) * 4);
        }
        cp_commit();
    }

    // -------- gold: gathered once from global (overlaps cp.async prologue) ----
    float gold = 0.f;
    {
        const int* tg = targets + b * TT;
        #pragma unroll
        for (int q = 0; q < 6; ++q) {
            int t = tid + q * NTH;
            if (t < len) {
                int v = __ldg(tg + t);
                gold += __ldg(fb + (size_t)t * TILESZ + v);
            }
        }
    }

    cp_wait4();
    __syncthreads();       // tile 0 visible

    // init packed carries s_0 = c_0 * 2^-4  (N_0 = 2^4), buffer 0
    if (tid < KK) {
        float c = ex2f(tile[KK * START_TAG + tid] * 1.4426950408889634f);
        __half h = __float2half_rn(c * 0.0625f);
        uint32_t hb = (uint32_t)__half_as_ushort(h);
        ch[tid] = hb | (hb << 16);
    }
    int eacc = 0;

    cp_wait3();
    __syncthreads();       // tile 1 visible

    // E for tile 1 (24 elements = 12 packed f16x2; i = u + 4*k)
    uint32_t E2[12];
    {
        const float* fn = tile + 1 * TILESZ + u * KK + 2 * p;
        #pragma unroll
        for (int k = 0; k < 12; ++k) {
            float2 f = *(const float2*)(fn + KK * 4 * k);
            E2[k] = ex2_cvt(f.x, f.y, L2E2);
        }
    }
    if (5 < len) {
        const float* src = fb + (size_t)5 * TILESZ;
        #pragma unroll
        for (int q = 0; q < 6; ++q)
            cp16(sb[5] + (tid + q * NTH) * 16, src + (tid + q * NTH) * 4);
    }
    cp_commit();

    int cur = 1;   // t % NB
    int pfb = 0;   // (t+5) % NB
    for (int t = 1; t < len; ++t) {
        cp_wait3();
        __syncthreads();     // carries(t-1) + tile t+1 visible; buffer pfb drained

        const int prev = (t - 1) & 1;
        const uint32_t* cr = ch + prev * KK;

        const uint32_t ch0 = cr[0];
        const int be = (int)((ch0 >> 10) & 31);
        eacc += be;

        // dot over 12 i-values (i = u + 4*k), both columns at once
        uint32_t aa = hmul2(E2[0], cr[u]);
        uint32_t bb = hmul2(E2[1], cr[u + 4]);
        aa = hfma2(E2[2],  cr[u + 8],  aa);
        bb = hfma2(E2[3],  cr[u + 12], bb);
        aa = hfma2(E2[4],  cr[u + 16], aa);
        bb = hfma2(E2[5],  cr[u + 20], bb);
        aa = hfma2(E2[6],  cr[u + 24], aa);
        bb = hfma2(E2[7],  cr[u + 28], bb);
        aa = hfma2(E2[8],  cr[u + 32], aa);
        bb = hfma2(E2[9],  cr[u + 36], bb);
        aa = hfma2(E2[10], cr[u + 40], aa);
        bb = hfma2(E2[11], cr[u + 44], bb);
        uint32_t acc = hadd2(aa, bb);

        const float* fn = tile + ((cur + 1 == NB) ? 0 : cur + 1) * TILESZ + u * KK + 2 * p;

        // E half 1 (k = 0..5) — issues while the dot chain drains
        #pragma unroll
        for (int k = 0; k < 6; ++k) {
            float2 f = *(const float2*)(fn + KK * 4 * k);
            E2[k] = ex2_cvt(f.x, f.y, L2E2);
        }

        acc = hadd2(acc, __shfl_xor_sync(0xffffffffu, acc, 8));

        // E half 2 (k = 6..11) — issues under shfl1's latency
        #pragma unroll
        for (int k = 6; k < 12; ++k) {
            float2 f = *(const float2*)(fn + KK * 4 * k);
            E2[k] = ex2_cvt(f.x, f.y, L2E2);
        }

        acc = hadd2(acc, __shfl_xor_sync(0xffffffffu, acc, 16));

        if (u == 0) {
            const uint32_t rb = (uint32_t)(22 - be) << 10;   // lagged renorm T = -8
            acc = hmul2(acc, rb | (rb << 16));
            uint32_t d0 = prmt(acc, 0x1010);   // (lo,lo) -> col 2p
            uint32_t d1 = prmt(acc, 0x3232);   // (hi,hi) -> col 2p+1
            *(uint2*)(ch + (t & 1) * KK + 2 * p) = make_uint2(d0, d1);
        }

        // prefetch tile t+5 (pure issue work, off the chain)
        {
            int tn = t + 5;
            if (tn < len) {
                const float* src = fb + (size_t)tn * TILESZ;
                uint32_t dst = sb[pfb];
                #pragma unroll
                for (int q = 0; q < 6; ++q)
                    cp16(dst + (tid + q * NTH) * 16, src + (tid + q * NTH) * 4);
            }
            cp_commit();
        }

        if (++cur == NB) cur = 0;
        if (++pfb == NB) pfb = 0;
    }

    // -------- gold reduction (deterministic fixed order) --------
    #pragma unroll
    for (int o = 16; o; o >>= 1) gold += __shfl_down_sync(0xffffffffu, gold, o);
    if (l == 0) gred[w] = gold;
    __syncthreads();

    if (tid == 0) {
        float g = (gred[0] + gred[1]) + gred[2];
        // ledger: lg2(c_last[stop]) = lg2(s_last[stop]) + 4 + sum(be) - 7*(len-1)
        uint32_t sw = ch[((len - 1) & 1) * KK + STOP_TAG];
        float s = __half2float(__ushort_as_half((unsigned short)(sw & 0xFFFF)));
        float fin = (lg2f(s) + 4.0f + (float)eacc - 7.0f * (float)(len - 1)) * LN2;
        g_partials[b] = fin - g;
    }

    // fused deterministic batch reduction (last block)
    if (tid < 32) {
        int old = 0;
        if (tid == 0) {
            __threadfence();
            old = atomicAdd(&g_ctr, 1);
        }
        old = __shfl_sync(0xffffffffu, old, 0);
        if (old == BB - 1) {
            __threadfence();
            float v = g_partials[tid];
            #pragma unroll
            for (int o = 16; o; o >>= 1) v += __shfl_down_sync(0xffffffffu, v, o);
            if (tid == 0) { out[0] = v / (float)BB; g_ctr = 0; }
        }
    }
}

extern "C" void kernel_launch(void* const* d_in, const int* in_sizes, int n_in,
                              void* d_out, int out_size)
{
    const float* feat    = (const float*)d_in[0];
    const int*   targets = (const int*)d_in[1];
    const int*   lengths = (const int*)d_in[2];
    float*       out     = (float*)d_out;

    const int smem_bytes = NB * TILESZ * 4 + 2 * KK * 4 + 16;  // ~55.7 KB
    cudaFuncSetAttribute(crf_fwd_kernel, cudaFuncAttributeMaxDynamicSharedMemorySize, smem_bytes);
    crf_fwd_kernel<<<BB, NTH, smem_bytes>>>(feat, targets, lengths, out);
}